// round 1
// baseline (speedup 1.0000x reference)
#include <cuda_runtime.h>
#include <math.h>

#define DIM_EI  4096
#define DIM_CA3 8192
#define DIM_CA1 8192
#define DIM_EO  4096

static constexpr float BETA  = 10.0f;
static constexpr float ALPHA = 0.01f;

// ---------------- device scratch (no allocations allowed) ----------------
__device__ float g_h1[DIM_CA3];
__device__ float g_h3[DIM_CA1];
__device__ float g_h2[DIM_CA1];
__device__ float g_h4[DIM_EO];
__device__ float g_xca3[DIM_CA3];
__device__ float g_IS[DIM_CA1];
__device__ float g_xca1[DIM_CA1];
__device__ float g_th[4];
__device__ int   g_nnz_idx[DIM_CA3];
__device__ float g_nnz_val[DIM_CA3];
__device__ int   g_nnz_cnt;

// ---------------- helpers ----------------
__device__ __forceinline__ unsigned f2u(float f) {
    unsigned u = __float_as_uint(f);
    return (u & 0x80000000u) ? ~u : (u | 0x80000000u);
}
__device__ __forceinline__ float u2f(unsigned u) {
    return __uint_as_float((u & 0x80000000u) ? (u & 0x7fffffffu) : ~u);
}

// Exact K-th largest of x[0..n) via 32-bit radix bit-select. One block,
// values cached in registers (n/blockDim <= 8). Deterministic.
__device__ float block_radix_kth(const float* __restrict__ x, int n, int K) {
    unsigned uv[8];
    int m = 0;
    for (int i = threadIdx.x; i < n; i += blockDim.x) uv[m++] = f2u(x[i]);

    __shared__ int s_cnt;
    unsigned prefix = 0;
    int k = K;
    for (int bit = 31; bit >= 0; --bit) {
        if (threadIdx.x == 0) s_cnt = 0;
        __syncthreads();
        unsigned bm = 1u << bit;
        unsigned hm = (bit == 31) ? 0u : ~((bm << 1) - 1u);
        int local = 0;
        #pragma unroll
        for (int j = 0; j < 8; j++) {
            if (j < m) {
                unsigned u = uv[j];
                local += (int)(((u & hm) == prefix) & ((u & bm) != 0u));
            }
        }
        #pragma unroll
        for (int o = 16; o; o >>= 1) local += __shfl_down_sync(0xffffffffu, local, o);
        if ((threadIdx.x & 31) == 0) atomicAdd(&s_cnt, local);
        __syncthreads();
        int c = s_cnt;
        if (c >= k) prefix |= bm; else k -= c;
        __syncthreads();
    }
    return u2f(prefix);
}

__device__ __forceinline__ float sigm(float z) { return 1.0f / (1.0f + expf(-z)); }

// ---------------- K1: h1 = W_ei_ca3 @ x, h3 = W_ei_ca1 @ x (one warp/row) ----------------
__global__ void matvec_dual_kernel(const float* __restrict__ Wa,
                                   const float* __restrict__ Wb,
                                   const float* __restrict__ x) {
    int warp = threadIdx.x >> 5, lane = threadIdx.x & 31;
    int row = blockIdx.x * 8 + warp;
    const float* W; float* out; int r;
    if (row < DIM_CA3) { W = Wa; out = g_h1; r = row; }
    else               { W = Wb; out = g_h3; r = row - DIM_CA3; }
    const float4* w4 = reinterpret_cast<const float4*>(W) + (size_t)r * (DIM_EI / 4);
    const float4* x4 = reinterpret_cast<const float4*>(x);
    float acc = 0.0f;
    #pragma unroll 8
    for (int i = lane; i < DIM_EI / 4; i += 32) {
        float4 w = w4[i], v = x4[i];
        acc += w.x * v.x + w.y * v.y + w.z * v.z + w.w * v.w;
    }
    #pragma unroll
    for (int o = 16; o; o >>= 1) acc += __shfl_down_sync(0xffffffffu, acc, o);
    if (lane == 0) out[r] = acc;
}

// ---------------- K2: top-K thresholds for h1/h3 + activations + x_ca3 compaction ----------------
__global__ void stageA_kernel() {
    if (blockIdx.x == 0) {
        float th = block_radix_kth(g_h1, DIM_CA3, 2);
        if (threadIdx.x == 0) g_th[0] = th;
        __shared__ int cnts[1024];
        int base = threadIdx.x * 8;
        float vals[8]; int keep[8]; int local = 0;
        #pragma unroll
        for (int k = 0; k < 8; k++) {
            float xx = g_h1[base + k];
            int kp = (xx >= th);
            float v = kp ? sigm(BETA * (xx - th)) : 0.0f;
            g_xca3[base + k] = v;
            vals[k] = v; keep[k] = kp; local += kp;
        }
        cnts[threadIdx.x] = local;
        __syncthreads();
        if (threadIdx.x == 0) {
            int s = 0;
            for (int i = 0; i < 1024; i++) { int c = cnts[i]; cnts[i] = s; s += c; }
            g_nnz_cnt = s;
        }
        __syncthreads();
        int o = cnts[threadIdx.x];
        #pragma unroll
        for (int k = 0; k < 8; k++) {
            if (keep[k]) { g_nnz_idx[o] = base + k; g_nnz_val[o] = vals[k]; ++o; }
        }
    } else {
        float th = block_radix_kth(g_h3, DIM_CA1, 100);
        if (threadIdx.x == 0) g_th[1] = th;
        for (int i = threadIdx.x; i < DIM_CA1; i += blockDim.x) {
            float xx = g_h3[i];
            g_IS[i] = (xx >= th) ? sigm(BETA * (xx - th)) : 0.0f;
        }
    }
}

// ---------------- K3: h2 via sparse column gather (x_ca3 has ~2 nonzeros) ----------------
__global__ void gather_h2_kernel(const float* __restrict__ W3) {
    int i = blockIdx.x * blockDim.x + threadIdx.x;
    if (i >= DIM_CA1) return;
    int cnt = g_nnz_cnt;
    float acc = 0.0f;
    for (int k = 0; k < cnt; k++)
        acc += W3[(size_t)i * DIM_CA3 + g_nnz_idx[k]] * g_nnz_val[k];
    g_h2[i] = acc;
}

// ---------------- K4: threshold h2 (K=100) + dense sigmoid (flag=False) ----------------
__global__ void stageC_kernel() {
    float th = block_radix_kth(g_h2, DIM_CA1, 100);
    if (threadIdx.x == 0) g_th[2] = th;
    for (int i = threadIdx.x; i < DIM_CA1; i += blockDim.x)
        g_xca1[i] = sigm(BETA * (g_h2[i] - th));
}

// ---------------- K5: W_new = a*W + b*x_ca3 (a=1,b=0 where IS==0 -> exact copy) ----------------
__global__ void update_W_kernel(const float* __restrict__ W, float* __restrict__ out) {
    size_t idx = ((size_t)blockIdx.x * blockDim.x + threadIdx.x) * 4;
    int row = (int)(idx >> 13);          // / 8192
    int col = (int)(idx & (DIM_CA3 - 1));
    float s = g_IS[row];
    float a = 1.0f - s * ALPHA;
    float b = ALPHA * s;
    float4 w  = *reinterpret_cast<const float4*>(W + idx);
    float4 xc = *reinterpret_cast<const float4*>(g_xca3 + col);
    float4 o;
    o.x = a * w.x + b * xc.x;
    o.y = a * w.y + b * xc.y;
    o.z = a * w.z + b * xc.z;
    o.w = a * w.w + b * xc.w;
    *reinterpret_cast<float4*>(out + idx) = o;
}

// ---------------- K6: h4 = W_ca1_eo @ x_ca1 ----------------
__global__ void matvec_out_kernel(const float* __restrict__ W) {
    int warp = threadIdx.x >> 5, lane = threadIdx.x & 31;
    int row = blockIdx.x * 8 + warp;
    const float4* w4 = reinterpret_cast<const float4*>(W) + (size_t)row * (DIM_CA1 / 4);
    const float4* x4 = reinterpret_cast<const float4*>(g_xca1);
    float acc = 0.0f;
    #pragma unroll 8
    for (int i = lane; i < DIM_CA1 / 4; i += 32) {
        float4 w = w4[i], v = x4[i];
        acc += w.x * v.x + w.y * v.y + w.z * v.z + w.w * v.w;
    }
    #pragma unroll
    for (int o = 16; o; o >>= 1) acc += __shfl_down_sync(0xffffffffu, acc, o);
    if (lane == 0) g_h4[row] = acc;
}

// ---------------- K7: threshold h4 (K=50) + masked sigmoid -> x_eo ----------------
__global__ void stageE_kernel(float* __restrict__ out) {
    float th = block_radix_kth(g_h4, DIM_EO, 50);
    if (threadIdx.x == 0) g_th[3] = th;
    for (int i = threadIdx.x; i < DIM_EO; i += blockDim.x) {
        float xx = g_h4[i];
        out[i] = (xx >= th) ? sigm(BETA * (xx - th)) : 0.0f;
    }
}

// ---------------- launch ----------------
extern "C" void kernel_launch(void* const* d_in, const int* in_sizes, int n_in,
                              void* d_out, int out_size) {
    const float* x_ei      = (const float*)d_in[0];
    const float* W_ei_ca3  = (const float*)d_in[1];
    const float* W_ei_ca1  = (const float*)d_in[2];
    const float* W_ca3_ca1 = (const float*)d_in[3];
    const float* W_ca1_eo  = (const float*)d_in[4];
    float* out = (float*)d_out;

    // h1, h3 (268 MB read, memory-bound)
    matvec_dual_kernel<<<(DIM_CA3 + DIM_CA1) / 8, 256>>>(W_ei_ca3, W_ei_ca1, x_ei);
    // top-2 / top-100 thresholds + x_ca3 (compacted) + IS
    stageA_kernel<<<2, 1024>>>();
    // h2 = 2-column gather of W_ca3_ca1
    gather_h2_kernel<<<DIM_CA1 / 256, 256>>>(W_ca3_ca1);
    // th(h2,100) + dense x_ca1
    stageC_kernel<<<1, 1024>>>();
    // W_new (536 MB, memory-bound)
    update_W_kernel<<<(unsigned)((size_t)DIM_CA1 * DIM_CA3 / 4 / 256), 256>>>(W_ca3_ca1, out + DIM_EO);
    // h4 (134 MB)
    matvec_out_kernel<<<DIM_EO / 8, 256>>>(W_ca1_eo);
    // th(h4,50) + x_eo
    stageE_kernel<<<1, 1024>>>(out);
}

// round 3
// speedup vs baseline: 1.2093x; 1.2093x over previous
#include <cuda_runtime.h>
#include <math.h>

#define DIM_EI  4096
#define DIM_CA3 8192
#define DIM_CA1 8192
#define DIM_EO  4096

static constexpr float BETA  = 10.0f;
static constexpr float ALPHA = 0.01f;

// ---------------- device scratch ----------------
__device__ float g_h1[DIM_CA3];
__device__ float g_h3[DIM_CA1];
__device__ float g_h4[DIM_EO];
__device__ float g_xca3[DIM_CA3];
__device__ float g_IS[DIM_CA1];
__device__ float g_xca1[DIM_CA1];
__device__ int   g_nnz_idx[DIM_CA3];
__device__ float g_nnz_val[DIM_CA3];
__device__ int   g_nnz_cnt;
__device__ unsigned g_ctr;

// ---------------- helpers ----------------
__device__ __forceinline__ unsigned f2u(float f) {
    unsigned u = __float_as_uint(f);
    return (u & 0x80000000u) ? ~u : (u | 0x80000000u);
}
__device__ __forceinline__ float u2f(unsigned u) {
    return __uint_as_float((u & 0x80000000u) ? (u & 0x7fffffffu) : ~u);
}
__device__ __forceinline__ float sigm(float z) { return 1.0f / (1.0f + expf(-z)); }

// Exact K-th largest via 4-pass radix-256 select over per-thread register
// values. All threads of the block must call. blockDim.x >= 256.
template<int M>
__device__ float kth_largest_radix256(const unsigned* uv, int K) {
    __shared__ unsigned s_hist[256];
    __shared__ int s_bin, s_k;
    unsigned prefix = 0;
    int k = K;
    #pragma unroll
    for (int shift = 24; shift >= 0; shift -= 8) {
        for (int b = threadIdx.x; b < 256; b += blockDim.x) s_hist[b] = 0;
        __syncthreads();
        unsigned hi = (shift == 24) ? 0u : (0xFFFFFFFFu << (shift + 8));
        #pragma unroll
        for (int j = 0; j < M; j++) {
            unsigned u = uv[j];
            if ((u & hi) == prefix) atomicAdd(&s_hist[(u >> shift) & 255], 1u);
        }
        __syncthreads();
        // parallel inclusive suffix sum: s_hist[b] = count(byte >= b)
        #pragma unroll
        for (int d = 1; d < 256; d <<= 1) {
            unsigned add = 0;
            if (threadIdx.x < 256)
                add = (threadIdx.x + d < 256) ? s_hist[threadIdx.x + d] : 0u;
            __syncthreads();
            if (threadIdx.x < 256) s_hist[threadIdx.x] += add;
            __syncthreads();
        }
        if (threadIdx.x < 256) {
            int b = threadIdx.x;
            unsigned ge = s_hist[b];
            unsigned gt = (b == 255) ? 0u : s_hist[b + 1];
            if (ge >= (unsigned)k && gt < (unsigned)k) { s_bin = b; s_k = k - (int)gt; }
        }
        __syncthreads();
        prefix |= ((unsigned)s_bin) << shift;
        k = s_k;
        __syncthreads();
    }
    return u2f(prefix);
}

// ---------------- K1: h1 = W_ei_ca3 @ x, h3 = W_ei_ca1 @ x (one warp/row) ----------------
__global__ void matvec_dual_kernel(const float* __restrict__ Wa,
                                   const float* __restrict__ Wb,
                                   const float* __restrict__ x) {
    int warp = threadIdx.x >> 5, lane = threadIdx.x & 31;
    int row = blockIdx.x * 8 + warp;
    const float* W; float* out; int r;
    if (row < DIM_CA3) { W = Wa; out = g_h1; r = row; }
    else               { W = Wb; out = g_h3; r = row - DIM_CA3; }
    const float4* w4 = reinterpret_cast<const float4*>(W) + (size_t)r * (DIM_EI / 4);
    const float4* x4 = reinterpret_cast<const float4*>(x);
    float acc = 0.0f;
    #pragma unroll 8
    for (int i = lane; i < DIM_EI / 4; i += 32) {
        float4 w = w4[i], v = x4[i];
        acc += w.x * v.x + w.y * v.y + w.z * v.z + w.w * v.w;
    }
    #pragma unroll
    for (int o = 16; o; o >>= 1) acc += __shfl_down_sync(0xffffffffu, acc, o);
    if (lane == 0) out[r] = acc;
}

// ---------------- K2: block0 -> top-2(h1)+x_ca3+compaction; block1 -> top-100(h3)+IS ----
__global__ void stageA_kernel() {
    __shared__ int wsum[32];
    int lane = threadIdx.x & 31, wid = threadIdx.x >> 5;
    int base = threadIdx.x * 8;
    if (blockIdx.x == 0) {
        float xv[8]; unsigned uv[8];
        #pragma unroll
        for (int j = 0; j < 8; j++) { xv[j] = g_h1[base + j]; uv[j] = f2u(xv[j]); }
        float th = kth_largest_radix256<8>(uv, 2);
        float vals[8]; int keep[8]; int cnt = 0;
        #pragma unroll
        for (int j = 0; j < 8; j++) {
            int kp = (xv[j] >= th);
            float v = kp ? sigm(BETA * (xv[j] - th)) : 0.0f;
            g_xca3[base + j] = v;
            vals[j] = v; keep[j] = kp; cnt += kp;
        }
        // deterministic compaction: warp inclusive scan + block scan of 32 warps
        int incl = cnt;
        #pragma unroll
        for (int o = 1; o < 32; o <<= 1) {
            int n = __shfl_up_sync(0xffffffffu, incl, o);
            if (lane >= o) incl += n;
        }
        if (lane == 31) wsum[wid] = incl;
        __syncthreads();
        if (threadIdx.x == 0) {
            int s = 0;
            #pragma unroll
            for (int i = 0; i < 32; i++) { int c = wsum[i]; wsum[i] = s; s += c; }
            g_nnz_cnt = s;
            g_ctr = 0;   // reset "last block" counter for matvec_out
        }
        __syncthreads();
        int off = wsum[wid] + incl - cnt;
        #pragma unroll
        for (int j = 0; j < 8; j++) {
            if (keep[j]) { g_nnz_idx[off] = base + j; g_nnz_val[off] = vals[j]; ++off; }
        }
    } else {
        float xv[8]; unsigned uv[8];
        #pragma unroll
        for (int j = 0; j < 8; j++) { xv[j] = g_h3[base + j]; uv[j] = f2u(xv[j]); }
        float th = kth_largest_radix256<8>(uv, 100);
        #pragma unroll
        for (int j = 0; j < 8; j++)
            g_IS[base + j] = (xv[j] >= th) ? sigm(BETA * (xv[j] - th)) : 0.0f;
    }
}

// ---------------- K3: fused h2 gather (x_ca3 ~2 nnz) + top-100 + dense sigmoid ----------
__global__ void stageBC_kernel(const float* __restrict__ W3) {
    int cnt = g_nnz_cnt;
    int base = threadIdx.x * 8;
    float hv[8]; unsigned uv[8];
    #pragma unroll
    for (int r = 0; r < 8; r++) {
        size_t rowoff = (size_t)(base + r) * DIM_CA3;
        float acc = 0.0f;
        for (int k = 0; k < cnt; k++)
            acc += W3[rowoff + g_nnz_idx[k]] * g_nnz_val[k];
        hv[r] = acc; uv[r] = f2u(acc);
    }
    float th = kth_largest_radix256<8>(uv, 100);
    #pragma unroll
    for (int r = 0; r < 8; r++)
        g_xca1[base + r] = sigm(BETA * (hv[r] - th));   // flag=False: no hard mask
}

// ---------------- K4: W_new = (1-IS*a)*W + a*IS*x_ca3^T (row-broadcast FMA) ----------
__global__ void update_W_kernel(const float* __restrict__ W, float* __restrict__ out) {
    size_t idx = ((size_t)blockIdx.x * blockDim.x + threadIdx.x) * 4;
    int row = (int)(idx >> 13);          // / 8192
    int col = (int)(idx & (DIM_CA3 - 1));
    float s = g_IS[row];
    float a = 1.0f - s * ALPHA;
    float b = ALPHA * s;
    float4 w  = *reinterpret_cast<const float4*>(W + idx);
    float4 xc = *reinterpret_cast<const float4*>(g_xca3 + col);
    float4 o;
    o.x = a * w.x + b * xc.x;
    o.y = a * w.y + b * xc.y;
    o.z = a * w.z + b * xc.z;
    o.w = a * w.w + b * xc.w;
    *reinterpret_cast<float4*>(out + idx) = o;
}

// ---------------- K5: h4 = W_ca1_eo @ x_ca1; last block: top-50 + masked sigmoid ------
__global__ void matvec_out_kernel(const float* __restrict__ W, float* __restrict__ out) {
    int warp = threadIdx.x >> 5, lane = threadIdx.x & 31;
    int row = blockIdx.x * 8 + warp;
    const float4* w4 = reinterpret_cast<const float4*>(W) + (size_t)row * (DIM_CA1 / 4);
    const float4* x4 = reinterpret_cast<const float4*>(g_xca1);
    float acc = 0.0f;
    #pragma unroll 8
    for (int i = lane; i < DIM_CA1 / 4; i += 32) {
        float4 w = w4[i], v = x4[i];
        acc += w.x * v.x + w.y * v.y + w.z * v.z + w.w * v.w;
    }
    #pragma unroll
    for (int o = 16; o; o >>= 1) acc += __shfl_down_sync(0xffffffffu, acc, o);
    if (lane == 0) {
        g_h4[row] = acc;
        __threadfence();
    }
    __syncthreads();
    __shared__ bool s_last;
    if (threadIdx.x == 0) {
        unsigned t = atomicAdd(&g_ctr, 1u);
        s_last = (t == gridDim.x - 1);
    }
    __syncthreads();
    if (!s_last) return;
    __threadfence();
    // final select over h4 (4096 elems, 256 threads, 16 each)
    int base = threadIdx.x * 16;
    float xv[16]; unsigned uv[16];
    #pragma unroll
    for (int j = 0; j < 16; j++) { xv[j] = g_h4[base + j]; uv[j] = f2u(xv[j]); }
    float th = kth_largest_radix256<16>(uv, 50);
    #pragma unroll
    for (int j = 0; j < 16; j++)
        out[base + j] = (xv[j] >= th) ? sigm(BETA * (xv[j] - th)) : 0.0f;
}

// ---------------- launch ----------------
extern "C" void kernel_launch(void* const* d_in, const int* in_sizes, int n_in,
                              void* d_out, int out_size) {
    const float* x_ei      = (const float*)d_in[0];
    const float* W_ei_ca3  = (const float*)d_in[1];
    const float* W_ei_ca1  = (const float*)d_in[2];
    const float* W_ca3_ca1 = (const float*)d_in[3];
    const float* W_ca1_eo  = (const float*)d_in[4];
    float* out = (float*)d_out;

    matvec_dual_kernel<<<(DIM_CA3 + DIM_CA1) / 8, 256>>>(W_ei_ca3, W_ei_ca1, x_ei);
    stageA_kernel<<<2, 1024>>>();
    stageBC_kernel<<<1, 1024>>>(W_ca3_ca1);
    update_W_kernel<<<(unsigned)((size_t)DIM_CA1 * DIM_CA3 / 4 / 256), 256>>>(W_ca3_ca1, out + DIM_EO);
    matvec_out_kernel<<<DIM_EO / 8, 256>>>(W_ca1_eo, out);
}

// round 4
// speedup vs baseline: 1.3575x; 1.1225x over previous
#include <cuda_runtime.h>
#include <math.h>

#define DIM_EI  4096
#define DIM_CA3 8192
#define DIM_CA1 8192
#define DIM_EO  4096

static constexpr float BETA  = 10.0f;
static constexpr float ALPHA = 0.01f;

// ---------------- device scratch ----------------
__device__ float g_h1[DIM_CA3];
__device__ float g_h3[DIM_CA1];
__device__ float g_h4[DIM_EO];
__device__ float g_xca3[DIM_CA3];
__device__ float g_IS[DIM_CA1];
__device__ float g_xca1[DIM_CA1];
__device__ int   g_nnz_idx[DIM_CA3];
__device__ float g_nnz_val[DIM_CA3];
__device__ int   g_nnz_cnt;
__device__ unsigned g_ctr;

// ---------------- helpers ----------------
__device__ __forceinline__ unsigned f2u(float f) {
    unsigned u = __float_as_uint(f);
    return (u & 0x80000000u) ? ~u : (u | 0x80000000u);
}
__device__ __forceinline__ float u2f(unsigned u) {
    return __uint_as_float((u & 0x80000000u) ? (u & 0x7fffffffu) : ~u);
}
__device__ __forceinline__ float sigm(float z) { return 1.0f / (1.0f + expf(-z)); }

// Exact K-th largest via 4-pass radix-256 select over per-thread register
// values. All threads of the block must call. blockDim.x >= 256.
template<int M>
__device__ float kth_largest_radix256(const unsigned* uv, int K) {
    __shared__ unsigned s_hist[256];
    __shared__ int s_bin, s_k;
    unsigned prefix = 0;
    int k = K;
    #pragma unroll
    for (int shift = 24; shift >= 0; shift -= 8) {
        for (int b = threadIdx.x; b < 256; b += blockDim.x) s_hist[b] = 0;
        __syncthreads();
        unsigned hi = (shift == 24) ? 0u : (0xFFFFFFFFu << (shift + 8));
        #pragma unroll
        for (int j = 0; j < M; j++) {
            unsigned u = uv[j];
            if ((u & hi) == prefix) atomicAdd(&s_hist[(u >> shift) & 255], 1u);
        }
        __syncthreads();
        // parallel inclusive suffix sum: s_hist[b] = count(byte >= b)
        #pragma unroll
        for (int d = 1; d < 256; d <<= 1) {
            unsigned add = 0;
            if (threadIdx.x < 256)
                add = (threadIdx.x + d < 256) ? s_hist[threadIdx.x + d] : 0u;
            __syncthreads();
            if (threadIdx.x < 256) s_hist[threadIdx.x] += add;
            __syncthreads();
        }
        if (threadIdx.x < 256) {
            int b = threadIdx.x;
            unsigned ge = s_hist[b];
            unsigned gt = (b == 255) ? 0u : s_hist[b + 1];
            if (ge >= (unsigned)k && gt < (unsigned)k) { s_bin = b; s_k = k - (int)gt; }
        }
        __syncthreads();
        prefix |= ((unsigned)s_bin) << shift;
        k = s_k;
        __syncthreads();
    }
    return u2f(prefix);
}

// ---------------- K1: h1 = W_ei_ca3 @ x, h3 = W_ei_ca1 @ x (one warp/row) ----------------
__global__ void matvec_dual_kernel(const float* __restrict__ Wa,
                                   const float* __restrict__ Wb,
                                   const float* __restrict__ x) {
    int warp = threadIdx.x >> 5, lane = threadIdx.x & 31;
    int row = blockIdx.x * 8 + warp;
    const float* W; float* out; int r;
    if (row < DIM_CA3) { W = Wa; out = g_h1; r = row; }
    else               { W = Wb; out = g_h3; r = row - DIM_CA3; }
    const float4* w4 = reinterpret_cast<const float4*>(W) + (size_t)r * (DIM_EI / 4);
    const float4* x4 = reinterpret_cast<const float4*>(x);
    float acc = 0.0f;
    #pragma unroll 8
    for (int i = lane; i < DIM_EI / 4; i += 32) {
        float4 w = __ldcs(&w4[i]);
        float4 v = __ldg(&x4[i]);
        acc += w.x * v.x + w.y * v.y + w.z * v.z + w.w * v.w;
    }
    #pragma unroll
    for (int o = 16; o; o >>= 1) acc += __shfl_down_sync(0xffffffffu, acc, o);
    if (lane == 0) out[r] = acc;
}

// ---------------- K2: block0 -> top-2(h1)+x_ca3+compaction; block1 -> top-100(h3)+IS ----
__global__ void stageA_kernel() {
    __shared__ int wsum[32];
    int lane = threadIdx.x & 31, wid = threadIdx.x >> 5;
    int base = threadIdx.x * 8;
    if (blockIdx.x == 0) {
        float xv[8]; unsigned uv[8];
        #pragma unroll
        for (int j = 0; j < 8; j++) { xv[j] = g_h1[base + j]; uv[j] = f2u(xv[j]); }
        float th = kth_largest_radix256<8>(uv, 2);
        float vals[8]; int keep[8]; int cnt = 0;
        #pragma unroll
        for (int j = 0; j < 8; j++) {
            int kp = (xv[j] >= th);
            float v = kp ? sigm(BETA * (xv[j] - th)) : 0.0f;
            g_xca3[base + j] = v;
            vals[j] = v; keep[j] = kp; cnt += kp;
        }
        // deterministic compaction: warp inclusive scan + block scan of 32 warps
        int incl = cnt;
        #pragma unroll
        for (int o = 1; o < 32; o <<= 1) {
            int n = __shfl_up_sync(0xffffffffu, incl, o);
            if (lane >= o) incl += n;
        }
        if (lane == 31) wsum[wid] = incl;
        __syncthreads();
        if (threadIdx.x == 0) {
            int s = 0;
            #pragma unroll
            for (int i = 0; i < 32; i++) { int c = wsum[i]; wsum[i] = s; s += c; }
            g_nnz_cnt = s;
            g_ctr = 0;   // reset "last block" counter for matvec_out
        }
        __syncthreads();
        int off = wsum[wid] + incl - cnt;
        #pragma unroll
        for (int j = 0; j < 8; j++) {
            if (keep[j]) { g_nnz_idx[off] = base + j; g_nnz_val[off] = vals[j]; ++off; }
        }
    } else {
        float xv[8]; unsigned uv[8];
        #pragma unroll
        for (int j = 0; j < 8; j++) { xv[j] = g_h3[base + j]; uv[j] = f2u(xv[j]); }
        float th = kth_largest_radix256<8>(uv, 100);
        #pragma unroll
        for (int j = 0; j < 8; j++)
            g_IS[base + j] = (xv[j] >= th) ? sigm(BETA * (xv[j] - th)) : 0.0f;
    }
}

// ---------------- K3: fused h2 gather (x_ca3 ~2 nnz) + top-100 + dense sigmoid ----------
__global__ void stageBC_kernel(const float* __restrict__ W3) {
    int cnt = g_nnz_cnt;
    int base = threadIdx.x * 8;
    float hv[8]; unsigned uv[8];
    #pragma unroll
    for (int r = 0; r < 8; r++) {
        size_t rowoff = (size_t)(base + r) * DIM_CA3;
        float acc = 0.0f;
        for (int k = 0; k < cnt; k++)
            acc += W3[rowoff + g_nnz_idx[k]] * g_nnz_val[k];
        hv[r] = acc; uv[r] = f2u(acc);
    }
    float th = kth_largest_radix256<8>(uv, 100);
    #pragma unroll
    for (int r = 0; r < 8; r++)
        g_xca1[base + r] = sigm(BETA * (hv[r] - th));   // flag=False: no hard mask
}

// ---------------- K4: W_new = (1-IS*a)*W + a*IS*x_ca3^T (row-broadcast FMA) ----------
__global__ void update_W_kernel(const float* __restrict__ W, float* __restrict__ out) {
    size_t idx = ((size_t)blockIdx.x * blockDim.x + threadIdx.x) * 4;
    int row = (int)(idx >> 13);          // / 8192
    int col = (int)(idx & (DIM_CA3 - 1));
    float s = g_IS[row];
    float a = 1.0f - s * ALPHA;
    float b = ALPHA * s;
    float4 w  = __ldcs(reinterpret_cast<const float4*>(W + idx));
    float4 xc = *reinterpret_cast<const float4*>(g_xca3 + col);
    float4 o;
    o.x = a * w.x + b * xc.x;
    o.y = a * w.y + b * xc.y;
    o.z = a * w.z + b * xc.z;
    o.w = a * w.w + b * xc.w;
    __stcs(reinterpret_cast<float4*>(out + idx), o);
}

// ---------------- K5: h4 = W_ca1_eo @ x_ca1; last block: top-50 + masked sigmoid ------
__global__ void matvec_out_kernel(const float* __restrict__ W, float* __restrict__ out) {
    int warp = threadIdx.x >> 5, lane = threadIdx.x & 31;
    int row = blockIdx.x * 8 + warp;
    const float4* w4 = reinterpret_cast<const float4*>(W) + (size_t)row * (DIM_CA1 / 4);
    const float4* x4 = reinterpret_cast<const float4*>(g_xca1);
    float acc = 0.0f;
    #pragma unroll 8
    for (int i = lane; i < DIM_CA1 / 4; i += 32) {
        float4 w = __ldcs(&w4[i]);
        float4 v = __ldg(&x4[i]);
        acc += w.x * v.x + w.y * v.y + w.z * v.z + w.w * v.w;
    }
    #pragma unroll
    for (int o = 16; o; o >>= 1) acc += __shfl_down_sync(0xffffffffu, acc, o);
    if (lane == 0) {
        g_h4[row] = acc;
        __threadfence();
    }
    __syncthreads();
    __shared__ bool s_last;
    if (threadIdx.x == 0) {
        unsigned t = atomicAdd(&g_ctr, 1u);
        s_last = (t == gridDim.x - 1);
    }
    __syncthreads();
    if (!s_last) return;
    __threadfence();
    // final select over h4 (4096 elems, 256 threads, 16 each)
    int base = threadIdx.x * 16;
    float xv[16]; unsigned uv[16];
    #pragma unroll
    for (int j = 0; j < 16; j++) { xv[j] = g_h4[base + j]; uv[j] = f2u(xv[j]); }
    float th = kth_largest_radix256<16>(uv, 50);
    #pragma unroll
    for (int j = 0; j < 16; j++)
        out[base + j] = (xv[j] >= th) ? sigm(BETA * (xv[j] - th)) : 0.0f;
}

// ---------------- launch: fork-join graph (B-chain hidden under update_W) -------------
extern "C" void kernel_launch(void* const* d_in, const int* in_sizes, int n_in,
                              void* d_out, int out_size) {
    const float* x_ei      = (const float*)d_in[0];
    const float* W_ei_ca3  = (const float*)d_in[1];
    const float* W_ei_ca1  = (const float*)d_in[2];
    const float* W_ca3_ca1 = (const float*)d_in[3];
    const float* W_ca1_eo  = (const float*)d_in[4];
    float* out = (float*)d_out;

    // Host-side stream/event lifecycle only runs during capture / the live
    // correctness call; graph replays carry none of this cost.
    cudaStream_t s1;
    cudaStreamCreateWithFlags(&s1, cudaStreamNonBlocking);
    cudaEvent_t e_fork, e_join;
    cudaEventCreateWithFlags(&e_fork, cudaEventDisableTiming);
    cudaEventCreateWithFlags(&e_join, cudaEventDisableTiming);

    matvec_dual_kernel<<<(DIM_CA3 + DIM_CA1) / 8, 256>>>(W_ei_ca3, W_ei_ca1, x_ei);
    stageA_kernel<<<2, 1024>>>();

    // fork: B-chain (stageBC -> matvec_out) concurrent with update_W
    cudaEventRecord(e_fork, 0);
    cudaStreamWaitEvent(s1, e_fork, 0);

    stageBC_kernel<<<1, 1024, 0, s1>>>(W_ca3_ca1);
    matvec_out_kernel<<<DIM_EO / 8, 256, 0, s1>>>(W_ca1_eo, out);

    update_W_kernel<<<(unsigned)((size_t)DIM_CA1 * DIM_CA3 / 4 / 256), 256>>>(W_ca3_ca1, out + DIM_EO);

    // join
    cudaEventRecord(e_join, s1);
    cudaStreamWaitEvent(0, e_join, 0);

    cudaEventDestroy(e_fork);
    cudaEventDestroy(e_join);
    cudaStreamDestroy(s1);
}